// round 16
// baseline (speedup 1.0000x reference)
#include <cuda_runtime.h>

typedef unsigned long long u64;

#define BT   256   // threads per block
#define XPT  2     // vectors per thread
#define NP   128   // codeword pairs
#define TILE (BT * XPT)

__device__ __forceinline__ u64 pk2(float lo, float hi) {
    u64 r;
    asm("mov.b64 %0, {%1, %2};" : "=l"(r) : "f"(lo), "f"(hi));
    return r;
}
__device__ __forceinline__ void upk2(u64 v, float& lo, float& hi) {
    asm("mov.b64 {%0, %1}, %2;" : "=f"(lo), "=f"(hi) : "l"(v));
}
// Blackwell packed fp32 FMA: 2 MACs per issue slot (the dense-issue workhorse)
__device__ __forceinline__ u64 ffma2(u64 a, u64 b, u64 c) {
    u64 d;
    asm("fma.rn.f32x2 %0, %1, %2, %3;" : "=l"(d) : "l"(a), "l"(b), "l"(c));
    return d;
}
// ||c||^2 with a FIXED IEEE op order — the only way q is ever computed.
__device__ __forceinline__ float qnorm(float4 a) {
    return __fmaf_rn(a.w, a.w, __fmaf_rn(a.z, a.z, __fmaf_rn(a.y, a.y, __fmul_rn(a.x, a.x))));
}

template <bool GUARD>
__global__ void __launch_bounds__(BT, 6)
vq_kernel(const float4* __restrict__ X,
          const float4* __restrict__ C,
          float4* __restrict__ outX,
          float* __restrict__ outS,
          int B)
{
    // Packed codebook: pair p covers codewords (2p, 2p+1)
    __shared__ ulonglong2 sAB[NP];      // (dim0 pair, dim1 pair)
    __shared__ ulonglong2 sCD[NP];      // (dim2 pair, dim3 pair)
    __shared__ ulonglong2 sQ2[NP / 2];  // ||c||^2 for pairs (2i,2i+1) in one 16B slot

    const int t = threadIdx.x;

    if (t < NP) {
        float4 a = C[2 * t];
        float4 b = C[2 * t + 1];
        sAB[t] = make_ulonglong2(pk2(a.x, b.x), pk2(a.y, b.y));
        sCD[t] = make_ulonglong2(pk2(a.z, b.z), pk2(a.w, b.w));
        u64 qp = pk2(qnorm(a), qnorm(b));
        if (t & 1) sQ2[t >> 1].y = qp; else sQ2[t >> 1].x = qp;
    }
    __syncthreads();

    const int base = blockIdx.x * TILE + t;

    u64 y0[XPT], y1[XPT], y2[XPT], y3[XPT];
    float bv[XPT];
    int   pid[XPT];

#pragma unroll
    for (int j = 0; j < XPT; j++) {
        int idx = base + j * BT;
        float4 x;
        if (GUARD) x = (idx < B) ? X[idx] : make_float4(0.f, 0.f, 0.f, 0.f);
        else       x = X[idx];
        float m0 = -2.0f * x.x, m1 = -2.0f * x.y, m2 = -2.0f * x.z, m3 = -2.0f * x.w;
        y0[j] = pk2(m0, m0);
        y1[j] = pk2(m1, m1);
        y2[j] = pk2(m2, m2);
        y3[j] = pk2(m3, m3);
        bv[j] = 3.402823466e38f;
        pid[j] = 0;
    }

    // Main loop: val_k = ||c_k||^2 - 2 x.c_k (same argmin as full distance).
    // Per pair per vector: 4 FFMA2 (fma pipe) + 4 short-latency alu — both at the
    // measured minimum for exact per-pair jnp.argmin semantics.
#pragma unroll 8
    for (int p2 = 0; p2 < NP / 2; p2++) {
        const ulonglong2 qq = sQ2[p2];   // broadcast LDS, conflict-free
        {
            const int p = 2 * p2;
            const ulonglong2 ab = sAB[p];
            const ulonglong2 cd = sCD[p];
#pragma unroll
            for (int j = 0; j < XPT; j++) {
                u64 acc = ffma2(y0[j], ab.x, qq.x);
                acc = ffma2(y1[j], ab.y, acc);
                acc = ffma2(y2[j], cd.x, acc);
                acc = ffma2(y3[j], cd.y, acc);
                float lo, hi;
                upk2(acc, lo, hi);
                float pv = fminf(lo, hi);
                if (pv < bv[j]) pid[j] = p;   // strict <: earlier pair wins ties
                bv[j] = fminf(bv[j], pv);     // FMNMX, lat 4
            }
        }
        {
            const int p = 2 * p2 + 1;
            const ulonglong2 ab = sAB[p];
            const ulonglong2 cd = sCD[p];
#pragma unroll
            for (int j = 0; j < XPT; j++) {
                u64 acc = ffma2(y0[j], ab.x, qq.y);
                acc = ffma2(y1[j], ab.y, acc);
                acc = ffma2(y2[j], cd.x, acc);
                acc = ffma2(y3[j], cd.y, acc);
                float lo, hi;
                upk2(acc, lo, hi);
                float pv = fminf(lo, hi);
                if (pv < bv[j]) pid[j] = p;
                bv[j] = fminf(bv[j], pv);
            }
        }
    }

    // Recovery: replay the winning pair's bitwise-identical FFMA2 chain (3 divergent
    // LDS per vector, once). FMNMX returns an input exactly, so hi<lo resolves the
    // within-pair index; ties prefer lo (= smaller index), matching jnp.argmin
    // first-occurrence. Winner components come from the pair registers (no gather).
#pragma unroll
    for (int j = 0; j < XPT; j++) {
        const int p = pid[j];
        const ulonglong2 rab = sAB[p];
        const ulonglong2 rcd = sCD[p];
        const ulonglong2 rqq = sQ2[p >> 1];
        const u64 rq = (p & 1) ? rqq.y : rqq.x;
        u64 acc = ffma2(y0[j], rab.x, rq);
        acc = ffma2(y1[j], rab.y, acc);
        acc = ffma2(y2[j], rcd.x, acc);
        acc = ffma2(y3[j], rcd.y, acc);
        float lo, hi;
        upk2(acc, lo, hi);
        const bool h = (hi < lo);
        float a0, b0, a1, b1, a2, b2, a3, b3;
        upk2(rab.x, a0, b0); upk2(rab.y, a1, b1);
        upk2(rcd.x, a2, b2); upk2(rcd.y, a3, b3);
        const int idx = base + j * BT;
        if (!GUARD || idx < B) {
            outX[idx] = make_float4(h ? b0 : a0, h ? b1 : a1,
                                    h ? b2 : a2, h ? b3 : a3);
            outS[idx] = (float)(2 * p + (h ? 1 : 0));   // harness reads d_out as f32
        }
    }
}

extern "C" void kernel_launch(void* const* d_in, const int* in_sizes, int n_in,
                              void* d_out, int out_size)
{
    const float4* X = (const float4*)d_in[0];   // [B, 4] fp32
    const float4* C = (const float4*)d_in[1];   // [256, 4] fp32 codebook

    const int B = in_sizes[0] / 4;

    float4* outX = (float4*)d_out;                  // hatX [B,4] fp32
    float*  outS = (float*)d_out + 4 * (size_t)B;   // state [B] as fp32

    if (B % TILE == 0) {
        vq_kernel<false><<<B / TILE, BT>>>(X, C, outX, outS, B);
    } else {
        vq_kernel<true><<<(B + TILE - 1) / TILE, BT>>>(X, C, outX, outS, B);
    }
}